// round 9
// baseline (speedup 1.0000x reference)
#include <cuda_runtime.h>
#include <cstdint>

#define BB 1024
#define TT 4096
#define SS 8
#define EE 8
#define PHS 64              // scan steps per cp.async phase
#define NPH (TT / PHS)
#define CPB 8               // chains per block (2 warps x 2 groups x 2 chains)
#define THREADS 64

// Scratch (no cudaMalloc allowed)
__device__ float g_preds[(size_t)BB * TT * SS];   // 134 MB trajectory
__device__ float g_dt[TT];

using ull = unsigned long long;

// ---------------- f32x2 packed helpers ----------------
__device__ __forceinline__ ull pk2(float lo, float hi) {
    ull r; asm("mov.b64 %0, {%1, %2};" : "=l"(r) : "f"(lo), "f"(hi)); return r;
}
__device__ __forceinline__ void up2(ull a, float& lo, float& hi) {
    asm("mov.b64 {%0, %1}, %2;" : "=f"(lo), "=f"(hi) : "l"(a));
}
__device__ __forceinline__ ull fma2(ull a, ull b, ull c) {
    ull r; asm("fma.rn.f32x2 %0, %1, %2, %3;" : "=l"(r) : "l"(a), "l"(b), "l"(c)); return r;
}
__device__ __forceinline__ ull mul2(ull a, ull b) {
    ull r; asm("mul.rn.f32x2 %0, %1, %2;" : "=l"(r) : "l"(a), "l"(b)); return r;
}
__device__ __forceinline__ ull add2(ull a, ull b) {
    ull r; asm("add.rn.f32x2 %0, %1, %2;" : "=l"(r) : "l"(a), "l"(b)); return r;
}

// tanh(x) = 1 - 2/(e^{2x}+1) via ex2.approx + rcp.approx (~1e-7 rel err)
__device__ __forceinline__ float fast_tanh(float z) {
    float e; asm("ex2.approx.f32 %0, %1;" : "=f"(e) : "f"(z * 2.8853900817779268f));
    float r; asm("rcp.approx.f32 %0, %1;" : "=f"(r) : "f"(e + 1.0f));
    return fmaf(-2.0f, r, 1.0f);
}

__device__ __forceinline__ void cpa16(void* dst, const void* src) {
    unsigned s = (unsigned)__cvta_generic_to_shared(dst);
    asm volatile("cp.async.cg.shared.global [%0], [%1], 16;" :: "r"(s), "l"(src));
}

// ---------------------------------------------------------------------------
__global__ void dt_kernel(const float* __restrict__ t) {
    int i = blockIdx.x * blockDim.x + threadIdx.x;
    if (i < TT) g_dt[i] = (i < TT - 1) ? (t[i + 1] - t[i]) : 0.0f;
}

// ---------------------------------------------------------------------------
// Sequential Euler scan. 16 lanes per chain-group; each group advances TWO
// independent chains (A, B) interleaved in software so one chain's compute
// issues inside the other chain's shuffle/tanh latency holes.
// Lane u (=lane&15) owns hidden units j = u and j = u+16 of both chains.
__global__ __launch_bounds__(THREADS, 1)
void scan_kernel(const float* __restrict__ x,    // [B,T,E]
                 const float* __restrict__ y0,   // [B,S]
                 const float* __restrict__ Wr1,  // [S+E, 32]
                 const float* __restrict__ br1,  // [32]
                 const float* __restrict__ Wr2,  // [32, S]
                 const float* __restrict__ br2)  // [S]
{
    __shared__ __align__(16) float sx[2][CPB][PHS * EE];  // 32 KB x-staging
    __shared__ __align__(16) float sdt[2][PHS];           // dt staging

    const int tid  = threadIdx.x;
    const int lane = tid & 31;
    const int wid  = tid >> 5;
    const int u    = lane & 15;                 // lane within 16-group
    const int grp  = lane >> 4;                 // group within warp
    const int gbase = (wid * 2 + grp) * 2;      // local index of chain A
    const int chainA = blockIdx.x * CPB + gbase;
    const int chainB = chainA + 1;

    // ---- register-resident weights (packed pairs), units j = u + 16m ----
    ull wy[2][4], we[2][4], w2p[2][4], b1p[2];
#pragma unroll
    for (int m = 0; m < 2; ++m) {
        const int j = u + 16 * m;
#pragma unroll
        for (int k = 0; k < 4; ++k) {
            wy[m][k]  = pk2(Wr1[(2 * k) * 32 + j],     Wr1[(2 * k + 1) * 32 + j]);
            we[m][k]  = pk2(Wr1[(8 + 2 * k) * 32 + j], Wr1[(9 + 2 * k) * 32 + j]);
            w2p[m][k] = pk2(Wr2[j * 8 + 2 * k],        Wr2[j * 8 + 2 * k + 1]);
        }
        b1p[m] = pk2(br1[j], 0.0f);   // bias in lo slot; hi stays 0 through the chain
    }
    ull b2p[4];
#pragma unroll
    for (int k = 0; k < 4; ++k) b2p[k] = pk2(br2[2 * k], br2[2 * k + 1]);

    // ---- initial states ----
    ull ypA[4], ypB[4];
    {
        const float4* qa = (const float4*)(y0 + (size_t)chainA * SS);
        const float4* qb = (const float4*)(y0 + (size_t)chainB * SS);
        float4 A0 = qa[0], A1 = qa[1], B0 = qb[0], B1 = qb[1];
        ypA[0] = pk2(A0.x, A0.y); ypA[1] = pk2(A0.z, A0.w);
        ypA[2] = pk2(A1.x, A1.y); ypA[3] = pk2(A1.z, A1.w);
        ypB[0] = pk2(B0.x, B0.y); ypB[1] = pk2(B0.z, B0.w);
        ypB[2] = pk2(B1.x, B1.y); ypB[3] = pk2(B1.z, B1.w);
    }

    // ---- phase staging: 8 chains x 512 floats = 1024 x 16B; 16 per thread ----
    auto issue = [&](int ph, int buf) {
#pragma unroll
        for (int q = 0; q < 16; ++q) {
            const int idx = tid + q * THREADS;    // 0..1023
            const int c   = idx >> 7;             // local chain
            const int off = idx & 127;            // 16B chunk within chain
            cpa16(&sx[buf][c][off * 4],
                  x + ((size_t)(blockIdx.x * CPB + c) * TT + (size_t)ph * PHS) * EE + off * 4);
        }
        if (tid < 16) cpa16(&sdt[buf][tid * 4], g_dt + ph * PHS + tid * 4);
        asm volatile("cp.async.commit_group;");
    };

    issue(0, 0);
    asm volatile("cp.async.wait_group 0;");
    __syncthreads();

    float* ppA = g_preds + (size_t)chainA * TT * SS;
    float* ppB = g_preds + (size_t)chainB * TT * SS;
    int buf = 0;

    for (int ph = 0; ph < NPH; ++ph) {
        if (ph + 1 < NPH) {
            issue(ph + 1, buf ^ 1);
            asm volatile("cp.async.wait_group 1;");
        }
        __syncthreads();
        const float* ebA = sx[buf][gbase];
        const float* ebB = sx[buf][gbase + 1];
        const float* dtb = sdt[buf];

#pragma unroll 2
        for (int i = 0; i < PHS; ++i) {
            // preds[b][t] = state BEFORE this step's update (preds[0] = y0)
            if (u == 0) {
                float f0, f1, f2, f3, f4, f5, f6, f7;
                up2(ypA[0], f0, f1); up2(ypA[1], f2, f3);
                up2(ypA[2], f4, f5); up2(ypA[3], f6, f7);
                float4* oa = (float4*)ppA;
                oa[0] = make_float4(f0, f1, f2, f3);
                oa[1] = make_float4(f4, f5, f6, f7);
                up2(ypB[0], f0, f1); up2(ypB[1], f2, f3);
                up2(ypB[2], f4, f5); up2(ypB[3], f6, f7);
                float4* ob = (float4*)ppB;
                ob[0] = make_float4(f0, f1, f2, f3);
                ob[1] = make_float4(f4, f5, f6, f7);
            }
            ppA += SS; ppB += SS;

            const float dt = dtb[i];
            const ull* epA = (const ull*)(ebA + i * 8);
            const ull* epB = (const ull*)(ebB + i * 8);
            const ull eA0 = epA[0], eA1 = epA[1], eA2 = epA[2], eA3 = epA[3];
            const ull eB0 = epB[0], eB1 = epB[1], eB2 = epB[2], eB3 = epB[3];

            // z/tanh for both chains (A and B chains are independent — the
            // scheduler interleaves them to cover fma/MUFU latency)
            float hA[2], hB[2];
#pragma unroll
            for (int m = 0; m < 2; ++m) {
                ull ca = fma2(eA0, we[m][0], b1p[m]);
                ull cb = fma2(eB0, we[m][0], b1p[m]);
                ca = fma2(eA1, we[m][1], ca);   cb = fma2(eB1, we[m][1], cb);
                ca = fma2(eA2, we[m][2], ca);   cb = fma2(eB2, we[m][2], cb);
                ca = fma2(eA3, we[m][3], ca);   cb = fma2(eB3, we[m][3], cb);
                ull aa = fma2(ypA[0], wy[m][0], ca);
                ull ab = fma2(ypB[0], wy[m][0], cb);
                aa = fma2(ypA[1], wy[m][1], aa); ab = fma2(ypB[1], wy[m][1], ab);
                aa = fma2(ypA[2], wy[m][2], aa); ab = fma2(ypB[2], wy[m][2], ab);
                aa = fma2(ypA[3], wy[m][3], aa); ab = fma2(ypB[3], wy[m][3], ab);
                float la, ha, lb, hb;
                up2(aa, la, ha); up2(ab, lb, hb);
                hA[m] = fast_tanh(la + ha);
                hB[m] = fast_tanh(lb + hb);
            }

            // partial rhs pairs
            const ull hA0 = pk2(hA[0], hA[0]), hA1 = pk2(hA[1], hA[1]);
            const ull hB0 = pk2(hB[0], hB[0]), hB1 = pk2(hB[1], hB[1]);
            ull pA[4], pB[4];
#pragma unroll
            for (int sp = 0; sp < 4; ++sp) {
                pA[sp] = fma2(hA1, w2p[1][sp], mul2(hA0, w2p[0][sp]));
                pB[sp] = fma2(hB1, w2p[1][sp], mul2(hB0, w2p[0][sp]));
            }

            // 4-round butterfly all-reduce in the 16-lane group, A/B interleaved
            // so one chain's SHFL latency is covered by the other's issue.
#pragma unroll
            for (int mask = 1; mask < 16; mask <<= 1) {
#pragma unroll
                for (int sp = 0; sp < 4; ++sp)
                    pA[sp] = add2(pA[sp], __shfl_xor_sync(0xffffffffu, pA[sp], mask));
#pragma unroll
                for (int sp = 0; sp < 4; ++sp)
                    pB[sp] = add2(pB[sp], __shfl_xor_sync(0xffffffffu, pB[sp], mask));
            }

            // Euler update (dt[T-1]=0 makes the final update a no-op)
            const ull dt2 = pk2(dt, dt);
#pragma unroll
            for (int sp = 0; sp < 4; ++sp) {
                ypA[sp] = fma2(dt2, add2(pA[sp], b2p[sp]), ypA[sp]);
                ypB[sp] = fma2(dt2, add2(pB[sp], b2p[sp]), ypB[sp]);
            }
        }
        __syncthreads();     // all reads of sx[buf] done before next issue overwrites it
        buf ^= 1;
    }
}

// ---------------------------------------------------------------------------
// Head: out = relu(preds @ W1 + b1) @ W2 + b2 — fully register-resident weights
__global__ __launch_bounds__(256)
void head_kernel(const float* __restrict__ W1, const float* __restrict__ b1,
                 const float* __restrict__ W2, const float* __restrict__ b2,
                 float* __restrict__ out)
{
    float w1[8][10], bb1[10], w2[10][2];
#pragma unroll
    for (int s = 0; s < 8; ++s)
#pragma unroll
        for (int i = 0; i < 10; ++i) w1[s][i] = __ldg(&W1[s * 10 + i]);
#pragma unroll
    for (int i = 0; i < 10; ++i) {
        bb1[i]   = __ldg(&b1[i]);
        w2[i][0] = __ldg(&W2[i * 2 + 0]);
        w2[i][1] = __ldg(&W2[i * 2 + 1]);
    }
    const float c0 = __ldg(&b2[0]), c1 = __ldg(&b2[1]);

    const int nt  = gridDim.x * blockDim.x;
    const int tid = blockIdx.x * blockDim.x + threadIdx.x;
    const int NPOS = BB * TT;

    for (int pos = tid; pos < NPOS; pos += nt) {
        const float4* ypt = (const float4*)(g_preds + (size_t)pos * SS);
        const float4 A = ypt[0], B = ypt[1];
        const float yv[8] = {A.x, A.y, A.z, A.w, B.x, B.y, B.z, B.w};
        float o0 = c0, o1 = c1;
#pragma unroll
        for (int i = 0; i < 10; ++i) {
            float hz = bb1[i];
#pragma unroll
            for (int s = 0; s < 8; ++s) hz = fmaf(yv[s], w1[s][i], hz);
            hz = fmaxf(hz, 0.0f);
            o0 = fmaf(hz, w2[i][0], o0);
            o1 = fmaf(hz, w2[i][1], o1);
        }
        *(float2*)(out + (size_t)pos * 2) = make_float2(o0, o1);
    }
}

// ---------------------------------------------------------------------------
extern "C" void kernel_launch(void* const* d_in, const int* in_sizes, int n_in,
                              void* d_out, int out_size) {
    const float* x   = (const float*)d_in[0];
    const float* t   = (const float*)d_in[1];
    const float* y0  = (const float*)d_in[2];
    const float* Wr1 = (const float*)d_in[3];
    const float* br1 = (const float*)d_in[4];
    const float* Wr2 = (const float*)d_in[5];
    const float* br2 = (const float*)d_in[6];
    const float* W1  = (const float*)d_in[7];
    const float* b1  = (const float*)d_in[8];
    const float* W2  = (const float*)d_in[9];
    const float* b2  = (const float*)d_in[10];
    float* out = (float*)d_out;

    dt_kernel<<<16, 256>>>(t);
    scan_kernel<<<BB / CPB, THREADS>>>(x, y0, Wr1, br1, Wr2, br2);
    head_kernel<<<2048, 256>>>(W1, b1, W2, b2, out);
}